// round 1
// baseline (speedup 1.0000x reference)
#include <cuda_runtime.h>
#include <cstddef>

#define NB 2
#define NC 128
#define NE 60000

// Scratch: transposed inputs [tensor][b*E+e][c] (contiguous 512B per edge row)
__device__ float g_xt[2][(size_t)NB * NE * NC];
// Effective fused weights: [branch][c][s*3+k], padded to 16 floats per (branch,c)
__device__ float g_V[2][NC][16];
// Fused bias constant per output k
__device__ float g_cb[3];

// ---------------------------------------------------------------------------
// Kernel 1: fold W_fuse into W_local / W_tri -> V, and all biases -> g_cb.
// V[t][c][s*3+k] = sum_o Wf[k][C+o]*Wtri[o][c][s]  (+ sum_o Wf[k][o]*Wlocal[o][c] for s==0)
// ---------------------------------------------------------------------------
__global__ void weights_kernel(
    const float* __restrict__ Wa_local, const float* __restrict__ ba_local,
    const float* __restrict__ Wb_local, const float* __restrict__ bb_local,
    const float* __restrict__ Wa_tri,   const float* __restrict__ ba_tri,
    const float* __restrict__ Wb_tri,   const float* __restrict__ bb_tri,
    const float* __restrict__ Wa_fuse,  const float* __restrict__ ba_fuse,
    const float* __restrict__ Wb_fuse,  const float* __restrict__ bb_fuse)
{
    int tid = blockIdx.x * blockDim.x + threadIdx.x;
    if (tid < 2 * NC * 15) {
        int t   = tid / (NC * 15);
        int rem = tid - t * (NC * 15);
        int c   = rem / 15;
        int sk  = rem - c * 15;
        int s   = sk / 3;
        int k   = sk - s * 3;
        const float* Wf = t ? Wb_fuse  : Wa_fuse;
        const float* Wt = t ? Wb_tri   : Wa_tri;
        const float* Wl = t ? Wb_local : Wa_local;
        float acc = 0.f;
        for (int o = 0; o < NC; o++)
            acc += Wf[k * (2 * NC) + NC + o] * Wt[(o * NC + c) * 5 + s];
        if (s == 0)
            for (int o = 0; o < NC; o++)
                acc += Wf[k * (2 * NC) + o] * Wl[o * NC + c];
        g_V[t][c][sk] = acc;
        if (sk == 0) g_V[t][c][15] = 0.f;  // pad lane
    }
    if (tid < 3) {
        float cb = ba_fuse[tid] + bb_fuse[tid];
        for (int o = 0; o < NC; o++) {
            cb += Wa_fuse[tid * 2 * NC + o]      * ba_local[o];
            cb += Wa_fuse[tid * 2 * NC + NC + o] * ba_tri[o];
            cb += Wb_fuse[tid * 2 * NC + o]      * bb_local[o];
            cb += Wb_fuse[tid * 2 * NC + NC + o] * bb_tri[o];
        }
        g_cb[tid] = cb;
    }
}

// ---------------------------------------------------------------------------
// Kernel 2: transpose x [B,C,E] -> g_xt [tensor][b][E][C]  (tiled, coalesced)
// grid: (E/32, C/32, 4)  z = tensor*2 + batch ; block (32,8)
// ---------------------------------------------------------------------------
__global__ void transpose_kernel(const float* __restrict__ x0,
                                 const float* __restrict__ x1)
{
    __shared__ float tile[32][33];
    const int z      = blockIdx.z;
    const int tensor = z >> 1;
    const int b      = z & 1;
    const float* __restrict__ src = tensor ? x1 : x0;
    const int e0 = blockIdx.x * 32;
    const int c0 = blockIdx.y * 32;

#pragma unroll
    for (int i = 0; i < 4; i++) {
        int c = c0 + threadIdx.y + 8 * i;
        tile[threadIdx.y + 8 * i][threadIdx.x] =
            src[((size_t)b * NC + c) * NE + e0 + threadIdx.x];
    }
    __syncthreads();
    float* __restrict__ dst = g_xt[tensor];
#pragma unroll
    for (int i = 0; i < 4; i++) {
        int e = e0 + threadIdx.y + 8 * i;
        dst[((size_t)b * NE + e) * NC + c0 + threadIdx.x] =
            tile[threadIdx.x][threadIdx.y + 8 * i];
    }
}

// ---------------------------------------------------------------------------
// Kernel 3: main gather + fused dot. One warp per (b,e); lane owns channels
// 4*lane..4*lane+3; the 120 effective weights live in registers.
// ---------------------------------------------------------------------------
__global__ void __launch_bounds__(128, 3)
mesh_main_kernel(const int* __restrict__ gemm, float* __restrict__ out)
{
    const int lane   = threadIdx.x & 31;
    const int warp   = blockIdx.x * 4 + (threadIdx.x >> 5);
    const int nwarps = gridDim.x * 4;

    // Load per-lane effective weights once (loop-invariant, register-resident)
    float Vv[2][4][16];
#pragma unroll
    for (int t = 0; t < 2; t++)
#pragma unroll
        for (int j = 0; j < 4; j++) {
            const float4* p = reinterpret_cast<const float4*>(g_V[t][4 * lane + j]);
            float4 q0 = p[0], q1 = p[1], q2 = p[2], q3 = p[3];
            Vv[t][j][0]  = q0.x; Vv[t][j][1]  = q0.y; Vv[t][j][2]  = q0.z; Vv[t][j][3]  = q0.w;
            Vv[t][j][4]  = q1.x; Vv[t][j][5]  = q1.y; Vv[t][j][6]  = q1.z; Vv[t][j][7]  = q1.w;
            Vv[t][j][8]  = q2.x; Vv[t][j][9]  = q2.y; Vv[t][j][10] = q2.z; Vv[t][j][11] = q2.w;
            Vv[t][j][12] = q3.x; Vv[t][j][13] = q3.y; Vv[t][j][14] = q3.z; Vv[t][j][15] = q3.w;
        }
    float cb = 0.f;
    if (lane < 3) cb = g_cb[lane];

    const int4* __restrict__ gi4 = reinterpret_cast<const int4*>(gemm);

    for (int i = warp; i < NB * NE; i += nwarps) {
        const int b = (i >= NE) ? 1 : 0;
        const int e = i - b * NE;
        const int4 gi = gi4[(size_t)b * NE + e];

        float r0 = 0.f, r1 = 0.f, r2 = 0.f;
#pragma unroll
        for (int t = 0; t < 2; t++) {
            const float* __restrict__ base =
                &g_xt[t][(size_t)b * NE * NC] + lane * 4;
            float4 xs = *reinterpret_cast<const float4*>(base + (size_t)e * NC);
            float4 n1 = *reinterpret_cast<const float4*>(base + (size_t)gi.x * NC);
            float4 n2 = *reinterpret_cast<const float4*>(base + (size_t)gi.y * NC);
            float4 n3 = *reinterpret_cast<const float4*>(base + (size_t)gi.z * NC);
            float4 n4 = *reinterpret_cast<const float4*>(base + (size_t)gi.w * NC);

            float g[5][4] = {
                { xs.x, xs.y, xs.z, xs.w },
                { n1.x + n3.x, n1.y + n3.y, n1.z + n3.z, n1.w + n3.w },
                { n2.x + n4.x, n2.y + n4.y, n2.z + n4.z, n2.w + n4.w },
                { fabsf(n1.x - n3.x), fabsf(n1.y - n3.y),
                  fabsf(n1.z - n3.z), fabsf(n1.w - n3.w) },
                { fabsf(n2.x - n4.x), fabsf(n2.y - n4.y),
                  fabsf(n2.z - n4.z), fabsf(n2.w - n4.w) },
            };

            float a0 = 0.f, a1 = 0.f, a2 = 0.f;
#pragma unroll
            for (int j = 0; j < 4; j++)
#pragma unroll
                for (int s = 0; s < 5; s++) {
                    float gv = g[s][j];
                    a0 = fmaf(Vv[t][j][s * 3 + 0], gv, a0);
                    a1 = fmaf(Vv[t][j][s * 3 + 1], gv, a1);
                    a2 = fmaf(Vv[t][j][s * 3 + 2], gv, a2);
                }
            r0 += a0; r1 += a1; r2 += a2;
        }

#pragma unroll
        for (int off = 16; off; off >>= 1) {
            r0 += __shfl_xor_sync(0xffffffffu, r0, off);
            r1 += __shfl_xor_sync(0xffffffffu, r1, off);
            r2 += __shfl_xor_sync(0xffffffffu, r2, off);
        }
        if (lane < 3) {
            float v = (lane == 0) ? r0 : (lane == 1) ? r1 : r2;
            out[((size_t)b * 3 + lane) * NE + e] = v + cb;
        }
    }
}

// ---------------------------------------------------------------------------
extern "C" void kernel_launch(void* const* d_in, const int* in_sizes, int n_in,
                              void* d_out, int out_size)
{
    const float* x_0      = (const float*)d_in[0];
    const float* x_1      = (const float*)d_in[1];
    const int*   gemm     = (const int*)  d_in[2];
    const float* Wa_local = (const float*)d_in[3];
    const float* ba_local = (const float*)d_in[4];
    const float* Wb_local = (const float*)d_in[5];
    const float* bb_local = (const float*)d_in[6];
    const float* Wa_tri   = (const float*)d_in[7];
    const float* ba_tri   = (const float*)d_in[8];
    const float* Wb_tri   = (const float*)d_in[9];
    const float* bb_tri   = (const float*)d_in[10];
    const float* Wa_fuse  = (const float*)d_in[11];
    const float* ba_fuse  = (const float*)d_in[12];
    const float* Wb_fuse  = (const float*)d_in[13];
    const float* bb_fuse  = (const float*)d_in[14];
    float* out = (float*)d_out;

    weights_kernel<<<16, 256>>>(Wa_local, ba_local, Wb_local, bb_local,
                                Wa_tri, ba_tri, Wb_tri, bb_tri,
                                Wa_fuse, ba_fuse, Wb_fuse, bb_fuse);

    transpose_kernel<<<dim3(NE / 32, NC / 32, 4), dim3(32, 8)>>>(x_0, x_1);

    mesh_main_kernel<<<444, 128>>>(gemm, out);
}

// round 2
// speedup vs baseline: 1.1831x; 1.1831x over previous
#include <cuda_runtime.h>
#include <cuda_fp16.h>
#include <cstddef>

#define NB 2
#define NC 128
#define NE 60000

// Scratch: transposed inputs in fp16 [tensor][b*E+e][c] (contiguous 256B per edge row)
__device__ __half g_xth[2][(size_t)NB * NE * NC];
// Effective fused weights: [branch][c][s*3+k], padded to 16 floats per (branch,c)
__device__ float g_V[2][NC][16];
// Fused bias constant per output k
__device__ float g_cb[3];

// ---------------------------------------------------------------------------
// Kernel 1: fold W_fuse into W_local / W_tri -> V, and all biases -> g_cb.
// One warp per output element; 128-term dot split 4 terms/lane + shuffle.
// ---------------------------------------------------------------------------
__global__ void weights_kernel(
    const float* __restrict__ Wa_local, const float* __restrict__ ba_local,
    const float* __restrict__ Wb_local, const float* __restrict__ bb_local,
    const float* __restrict__ Wa_tri,   const float* __restrict__ ba_tri,
    const float* __restrict__ Wb_tri,   const float* __restrict__ bb_tri,
    const float* __restrict__ Wa_fuse,  const float* __restrict__ ba_fuse,
    const float* __restrict__ Wb_fuse,  const float* __restrict__ bb_fuse)
{
    const int lane = threadIdx.x & 31;
    const int w = (blockIdx.x * blockDim.x + threadIdx.x) >> 5;

    if (w < 2 * NC * 15) {
        const int t   = w / (NC * 15);
        const int rem = w - t * (NC * 15);
        const int c   = rem / 15;
        const int sk  = rem - c * 15;
        const int s   = sk / 3;
        const int k   = sk - s * 3;
        const float* Wf = t ? Wb_fuse  : Wa_fuse;
        const float* Wt = t ? Wb_tri   : Wa_tri;
        const float* Wl = t ? Wb_local : Wa_local;
        float acc = 0.f;
#pragma unroll
        for (int j = 0; j < 4; j++) {
            int o = lane + 32 * j;
            acc = fmaf(Wf[k * (2 * NC) + NC + o], Wt[(o * NC + c) * 5 + s], acc);
            if (s == 0)
                acc = fmaf(Wf[k * (2 * NC) + o], Wl[o * NC + c], acc);
        }
#pragma unroll
        for (int off = 16; off; off >>= 1)
            acc += __shfl_xor_sync(0xffffffffu, acc, off);
        if (lane == 0) {
            g_V[t][c][sk] = acc;
            if (sk == 0) g_V[t][c][15] = 0.f;  // pad lane
        }
    } else if (w < 2 * NC * 15 + 3) {
        const int k = w - 2 * NC * 15;
        float acc = 0.f;
#pragma unroll
        for (int j = 0; j < 4; j++) {
            int o = lane + 32 * j;
            acc = fmaf(Wa_fuse[k * 2 * NC + o],      ba_local[o], acc);
            acc = fmaf(Wa_fuse[k * 2 * NC + NC + o], ba_tri[o],   acc);
            acc = fmaf(Wb_fuse[k * 2 * NC + o],      bb_local[o], acc);
            acc = fmaf(Wb_fuse[k * 2 * NC + NC + o], bb_tri[o],   acc);
        }
#pragma unroll
        for (int off = 16; off; off >>= 1)
            acc += __shfl_xor_sync(0xffffffffu, acc, off);
        if (lane == 0)
            g_cb[k] = acc + ba_fuse[k] + bb_fuse[k];
    }
}

// ---------------------------------------------------------------------------
// Kernel 2: transpose x [B,C,E] fp32 -> g_xth [tensor][b][E][C] fp16
// grid: (E/32, C/32, 4)  z = tensor*2 + batch ; block (32,8)
// ---------------------------------------------------------------------------
__global__ void transpose_kernel(const float* __restrict__ x0,
                                 const float* __restrict__ x1)
{
    __shared__ float tile[32][33];
    const int z      = blockIdx.z;
    const int tensor = z >> 1;
    const int b      = z & 1;
    const float* __restrict__ src = tensor ? x1 : x0;
    const int e0 = blockIdx.x * 32;
    const int c0 = blockIdx.y * 32;

#pragma unroll
    for (int i = 0; i < 4; i++) {
        int c = c0 + threadIdx.y + 8 * i;
        tile[threadIdx.y + 8 * i][threadIdx.x] =
            src[((size_t)b * NC + c) * NE + e0 + threadIdx.x];
    }
    __syncthreads();
    __half* __restrict__ dst = g_xth[tensor];
#pragma unroll
    for (int i = 0; i < 4; i++) {
        int e = e0 + threadIdx.y + 8 * i;
        dst[((size_t)b * NE + e) * NC + c0 + threadIdx.x] =
            __float2half_rn(tile[threadIdx.x][threadIdx.y + 8 * i]);
    }
}

// ---------------------------------------------------------------------------
// Kernel 3: main gather + fused dot. One warp per (b,e); lane owns channels
// 4*lane..4*lane+3; the 120 effective weights live in registers (occ 2 to
// avoid spilling the 128-float Vv array).
// ---------------------------------------------------------------------------
__device__ __forceinline__ float4 ld4h(const __half* __restrict__ p)
{
    uint2 u = *reinterpret_cast<const uint2*>(p);
    __half2 h0 = *reinterpret_cast<const __half2*>(&u.x);
    __half2 h1 = *reinterpret_cast<const __half2*>(&u.y);
    float2 f0 = __half22float2(h0);
    float2 f1 = __half22float2(h1);
    return make_float4(f0.x, f0.y, f1.x, f1.y);
}

__global__ void __launch_bounds__(128, 2)
mesh_main_kernel(const int* __restrict__ gemm, float* __restrict__ out)
{
    const int lane   = threadIdx.x & 31;
    const int warp   = blockIdx.x * 4 + (threadIdx.x >> 5);
    const int nwarps = gridDim.x * 4;

    // Load per-lane effective weights once (loop-invariant, register-resident)
    float Vv[2][4][16];
#pragma unroll
    for (int t = 0; t < 2; t++)
#pragma unroll
        for (int j = 0; j < 4; j++) {
            const float4* p = reinterpret_cast<const float4*>(g_V[t][4 * lane + j]);
            float4 q0 = p[0], q1 = p[1], q2 = p[2], q3 = p[3];
            Vv[t][j][0]  = q0.x; Vv[t][j][1]  = q0.y; Vv[t][j][2]  = q0.z; Vv[t][j][3]  = q0.w;
            Vv[t][j][4]  = q1.x; Vv[t][j][5]  = q1.y; Vv[t][j][6]  = q1.z; Vv[t][j][7]  = q1.w;
            Vv[t][j][8]  = q2.x; Vv[t][j][9]  = q2.y; Vv[t][j][10] = q2.z; Vv[t][j][11] = q2.w;
            Vv[t][j][12] = q3.x; Vv[t][j][13] = q3.y; Vv[t][j][14] = q3.z; Vv[t][j][15] = q3.w;
        }
    float cb = 0.f;
    if (lane < 3) cb = g_cb[lane];

    const int4* __restrict__ gi4 = reinterpret_cast<const int4*>(gemm);

    for (int i = warp; i < NB * NE; i += nwarps) {
        const int b = (i >= NE) ? 1 : 0;
        const int e = i - b * NE;
        const int4 gi = gi4[(size_t)b * NE + e];

        float r0 = 0.f, r1 = 0.f, r2 = 0.f;
#pragma unroll
        for (int t = 0; t < 2; t++) {
            const __half* __restrict__ base =
                &g_xth[t][(size_t)b * NE * NC] + lane * 4;
            float4 xs = ld4h(base + (size_t)e * NC);
            float4 n1 = ld4h(base + (size_t)gi.x * NC);
            float4 n2 = ld4h(base + (size_t)gi.y * NC);
            float4 n3 = ld4h(base + (size_t)gi.z * NC);
            float4 n4 = ld4h(base + (size_t)gi.w * NC);

            float g[5][4] = {
                { xs.x, xs.y, xs.z, xs.w },
                { n1.x + n3.x, n1.y + n3.y, n1.z + n3.z, n1.w + n3.w },
                { n2.x + n4.x, n2.y + n4.y, n2.z + n4.z, n2.w + n4.w },
                { fabsf(n1.x - n3.x), fabsf(n1.y - n3.y),
                  fabsf(n1.z - n3.z), fabsf(n1.w - n3.w) },
                { fabsf(n2.x - n4.x), fabsf(n2.y - n4.y),
                  fabsf(n2.z - n4.z), fabsf(n2.w - n4.w) },
            };

            float a0 = 0.f, a1 = 0.f, a2 = 0.f;
#pragma unroll
            for (int j = 0; j < 4; j++)
#pragma unroll
                for (int s = 0; s < 5; s++) {
                    float gv = g[s][j];
                    a0 = fmaf(Vv[t][j][s * 3 + 0], gv, a0);
                    a1 = fmaf(Vv[t][j][s * 3 + 1], gv, a1);
                    a2 = fmaf(Vv[t][j][s * 3 + 2], gv, a2);
                }
            r0 += a0; r1 += a1; r2 += a2;
        }

#pragma unroll
        for (int off = 16; off; off >>= 1) {
            r0 += __shfl_xor_sync(0xffffffffu, r0, off);
            r1 += __shfl_xor_sync(0xffffffffu, r1, off);
            r2 += __shfl_xor_sync(0xffffffffu, r2, off);
        }
        if (lane < 3) {
            float v = (lane == 0) ? r0 : (lane == 1) ? r1 : r2;
            out[((size_t)b * 3 + lane) * NE + e] = v + cb;
        }
    }
}

// ---------------------------------------------------------------------------
extern "C" void kernel_launch(void* const* d_in, const int* in_sizes, int n_in,
                              void* d_out, int out_size)
{
    const float* x_0      = (const float*)d_in[0];
    const float* x_1      = (const float*)d_in[1];
    const int*   gemm     = (const int*)  d_in[2];
    const float* Wa_local = (const float*)d_in[3];
    const float* ba_local = (const float*)d_in[4];
    const float* Wb_local = (const float*)d_in[5];
    const float* bb_local = (const float*)d_in[6];
    const float* Wa_tri   = (const float*)d_in[7];
    const float* ba_tri   = (const float*)d_in[8];
    const float* Wb_tri   = (const float*)d_in[9];
    const float* bb_tri   = (const float*)d_in[10];
    const float* Wa_fuse  = (const float*)d_in[11];
    const float* ba_fuse  = (const float*)d_in[12];
    const float* Wb_fuse  = (const float*)d_in[13];
    const float* bb_fuse  = (const float*)d_in[14];
    float* out = (float*)d_out;

    // (2*128*15 + 3) warps of work, 8 warps per block
    weights_kernel<<<(2 * NC * 15 + 3 + 7) / 8, 256>>>(
        Wa_local, ba_local, Wb_local, bb_local,
        Wa_tri, ba_tri, Wb_tri, bb_tri,
        Wa_fuse, ba_fuse, Wb_fuse, bb_fuse);

    transpose_kernel<<<dim3(NE / 32, NC / 32, 4), dim3(32, 8)>>>(x_0, x_1);

    mesh_main_kernel<<<296, 128>>>(gemm, out);
}

// round 3
// speedup vs baseline: 1.9247x; 1.6268x over previous
#include <cuda_runtime.h>
#include <cuda_fp16.h>
#include <cstddef>

#define NB 2
#define NC 128
#define NE 60000
#define TR_BLOCKS (NB * 2 * (NE / 32) * (NC / 32))   // 30000 transpose tiles
#define W_WARPS   (2 * NC * 15 + 3)                  // 3843 weight warps
#define W_BLOCKS  ((W_WARPS + 7) / 8)                // 481
#define GROUPS    (NB * NE / 4)                      // 30000 4-edge groups

// Transposed inputs in fp16: [tensor][b*E+e][c] (256B per edge row)
__device__ __half g_xth[2][(size_t)NB * NE * NC];
// Effective fused weights: [branch][c][s*3+k] padded to 16
__device__ float g_V[2][NC][16];
__device__ float g_cb[3];

// ---------------------------------------------------------------------------
// Kernel 1 (fused): blocks < TR_BLOCKS transpose x->fp16; the rest fold weights.
// ---------------------------------------------------------------------------
__global__ void __launch_bounds__(256)
prep_kernel(const float* __restrict__ x0, const float* __restrict__ x1,
    const float* __restrict__ Wa_local, const float* __restrict__ ba_local,
    const float* __restrict__ Wb_local, const float* __restrict__ bb_local,
    const float* __restrict__ Wa_tri,   const float* __restrict__ ba_tri,
    const float* __restrict__ Wb_tri,   const float* __restrict__ bb_tri,
    const float* __restrict__ Wa_fuse,  const float* __restrict__ ba_fuse,
    const float* __restrict__ Wb_fuse,  const float* __restrict__ bb_fuse)
{
    if (blockIdx.x < TR_BLOCKS) {
        // ---- transpose tile: [32c x 32e] of one (tensor,b) ----
        __shared__ float tile[32][33];
        const int tx = threadIdx.x & 31;
        const int ty = threadIdx.x >> 5;
        int bx = blockIdx.x;
        const int eb  = bx % (NE / 32);  bx /= (NE / 32);
        const int cbk = bx & 3;          bx >>= 2;
        const int tensor = bx >> 1;
        const int b      = bx & 1;
        const float* __restrict__ src = tensor ? x1 : x0;
        const int e0 = eb * 32, c0 = cbk * 32;

#pragma unroll
        for (int i = 0; i < 4; i++) {
            int c = c0 + ty + 8 * i;
            tile[ty + 8 * i][tx] = src[((size_t)b * NC + c) * NE + e0 + tx];
        }
        __syncthreads();
        __half* __restrict__ dst = g_xth[tensor];
#pragma unroll
        for (int i = 0; i < 4; i++) {
            int e = e0 + ty + 8 * i;
            dst[((size_t)b * NE + e) * NC + c0 + tx] =
                __float2half_rn(tile[tx][ty + 8 * i]);
        }
        return;
    }

    // ---- weight folding: one warp per output ----
    const int lane = threadIdx.x & 31;
    const int w = (blockIdx.x - TR_BLOCKS) * 8 + (threadIdx.x >> 5);

    if (w < 2 * NC * 15) {
        const int t   = w / (NC * 15);
        const int rem = w - t * (NC * 15);
        const int c   = rem / 15;
        const int sk  = rem - c * 15;
        const int s   = sk / 3;
        const int k   = sk - s * 3;
        const float* Wf = t ? Wb_fuse  : Wa_fuse;
        const float* Wt = t ? Wb_tri   : Wa_tri;
        const float* Wl = t ? Wb_local : Wa_local;
        float acc = 0.f;
#pragma unroll
        for (int j = 0; j < 4; j++) {
            int o = lane + 32 * j;
            acc = fmaf(Wf[k * (2 * NC) + NC + o], Wt[(o * NC + c) * 5 + s], acc);
            if (s == 0)
                acc = fmaf(Wf[k * (2 * NC) + o], Wl[o * NC + c], acc);
        }
#pragma unroll
        for (int off = 16; off; off >>= 1)
            acc += __shfl_xor_sync(0xffffffffu, acc, off);
        if (lane == 0) {
            g_V[t][c][sk] = acc;
            if (sk == 0) g_V[t][c][15] = 0.f;
        }
    } else if (w < 2 * NC * 15 + 3) {
        const int k = w - 2 * NC * 15;
        float acc = 0.f;
#pragma unroll
        for (int j = 0; j < 4; j++) {
            int o = lane + 32 * j;
            acc = fmaf(Wa_fuse[k * 2 * NC + o],      ba_local[o], acc);
            acc = fmaf(Wa_fuse[k * 2 * NC + NC + o], ba_tri[o],   acc);
            acc = fmaf(Wb_fuse[k * 2 * NC + o],      bb_local[o], acc);
            acc = fmaf(Wb_fuse[k * 2 * NC + NC + o], bb_tri[o],   acc);
        }
#pragma unroll
        for (int off = 16; off; off >>= 1)
            acc += __shfl_xor_sync(0xffffffffu, acc, off);
        if (lane == 0)
            g_cb[k] = acc + ba_fuse[k] + bb_fuse[k];
    }
}

// ---------------------------------------------------------------------------
// Kernel 2: main gather + fused dot.
// 256-thread blocks = 8 warps = 4 warp-pairs. Warp w: tensor t=w>>2, pair p=w&3.
// Each pair processes aligned groups of 4 edges; each warp computes its
// tensor's contribution (lane owns 4 channels, 60 weights in registers),
// pairs combine via double-buffered smem.
// ---------------------------------------------------------------------------
__device__ __forceinline__ void ld2h2(const __half* __restrict__ p,
                                      __half2& a, __half2& b)
{
    uint2 u = *reinterpret_cast<const uint2*>(p);
    a = *reinterpret_cast<const __half2*>(&u.x);
    b = *reinterpret_cast<const __half2*>(&u.y);
}

__global__ void __launch_bounds__(256, 2)
mesh_main_kernel(const int* __restrict__ gemm, float* __restrict__ out)
{
    __shared__ float partial[2][2][4][12];   // [buf][t][pair][u*3+k]

    const int lane = threadIdx.x & 31;
    const int wid  = threadIdx.x >> 5;
    const int t    = wid >> 2;
    const int p    = wid & 3;
    const int pairIdx = blockIdx.x * 4 + p;
    const int P       = gridDim.x * 4;
    const int nIter   = (GROUPS + P - 1) / P;

    // own-tensor weights: 64 registers
    float Vv[4][16];
#pragma unroll
    for (int j = 0; j < 4; j++) {
        const float4* q = reinterpret_cast<const float4*>(g_V[t][4 * lane + j]);
        float4 q0 = q[0], q1 = q[1], q2 = q[2], q3 = q[3];
        Vv[j][0]  = q0.x; Vv[j][1]  = q0.y; Vv[j][2]  = q0.z; Vv[j][3]  = q0.w;
        Vv[j][4]  = q1.x; Vv[j][5]  = q1.y; Vv[j][6]  = q1.z; Vv[j][7]  = q1.w;
        Vv[j][8]  = q2.x; Vv[j][9]  = q2.y; Vv[j][10] = q2.z; Vv[j][11] = q2.w;
        Vv[j][12] = q3.x; Vv[j][13] = q3.y; Vv[j][14] = q3.z; Vv[j][15] = q3.w;
    }
    float cbk = (lane < 12) ? g_cb[lane % 3] : 0.f;

    const int4* __restrict__ gi4 = reinterpret_cast<const int4*>(gemm);
    const __half* __restrict__ xt = g_xth[t];

    int buf = 0;
    for (int it = 0; it < nIter; it++, buf ^= 1) {
        const int g = pairIdx + it * P;
        const bool active = (g < GROUPS);
        int b = 0, ebase = 0;

        if (active) {
            const int e0 = 4 * g;
            b     = (e0 >= NE) ? 1 : 0;
            ebase = e0 - b * NE;
            const __half* __restrict__ base =
                xt + (size_t)b * NE * NC + lane * 4;

            float res[12];
#pragma unroll
            for (int u = 0; u < 4; u++) {
                const int e = ebase + u;
                const int4 gi = gi4[(size_t)b * NE + e];

                __half2 xs0, xs1, n10, n11, n20, n21, n30, n31, n40, n41;
                ld2h2(base + (size_t)e    * NC, xs0, xs1);
                ld2h2(base + (size_t)gi.x * NC, n10, n11);
                ld2h2(base + (size_t)gi.y * NC, n20, n21);
                ld2h2(base + (size_t)gi.z * NC, n30, n31);
                ld2h2(base + (size_t)gi.w * NC, n40, n41);

                __half2 s10 = __hadd2(n10, n30), s11 = __hadd2(n11, n31);
                __half2 s20 = __hadd2(n20, n40), s21 = __hadd2(n21, n41);
                __half2 d10 = __habs2(__hsub2(n10, n30));
                __half2 d11 = __habs2(__hsub2(n11, n31));
                __half2 d20 = __habs2(__hsub2(n20, n40));
                __half2 d21 = __habs2(__hsub2(n21, n41));

                float2 G0a = __half22float2(xs0), G0b = __half22float2(xs1);
                float2 G1a = __half22float2(s10), G1b = __half22float2(s11);
                float2 G2a = __half22float2(s20), G2b = __half22float2(s21);
                float2 G3a = __half22float2(d10), G3b = __half22float2(d11);
                float2 G4a = __half22float2(d20), G4b = __half22float2(d21);

                const float gm[5][4] = {
                    { G0a.x, G0a.y, G0b.x, G0b.y },
                    { G1a.x, G1a.y, G1b.x, G1b.y },
                    { G2a.x, G2a.y, G2b.x, G2b.y },
                    { G3a.x, G3a.y, G3b.x, G3b.y },
                    { G4a.x, G4a.y, G4b.x, G4b.y },
                };

                float a0 = 0.f, a1 = 0.f, a2 = 0.f;
#pragma unroll
                for (int j = 0; j < 4; j++)
#pragma unroll
                    for (int s = 0; s < 5; s++) {
                        float gv = gm[s][j];
                        a0 = fmaf(Vv[j][s * 3 + 0], gv, a0);
                        a1 = fmaf(Vv[j][s * 3 + 1], gv, a1);
                        a2 = fmaf(Vv[j][s * 3 + 2], gv, a2);
                    }
                res[u * 3 + 0] = a0;
                res[u * 3 + 1] = a1;
                res[u * 3 + 2] = a2;
            }

            // reduce all 12 values (independent chains interleave)
#pragma unroll
            for (int off = 16; off; off >>= 1)
#pragma unroll
                for (int r = 0; r < 12; r++)
                    res[r] += __shfl_xor_sync(0xffffffffu, res[r], off);

            if (lane == 0) {
#pragma unroll
                for (int r = 0; r < 12; r++)
                    partial[buf][t][p][r] = res[r];
            }
        }
        __syncthreads();

        if (active && t == 0 && lane < 12) {
            const int u = lane / 3, k = lane - 3 * u;
            float v = partial[buf][0][p][lane] + partial[buf][1][p][lane] + cbk;
            out[((size_t)b * 3 + k) * NE + ebase + u] = v;
        }
    }
}

// ---------------------------------------------------------------------------
extern "C" void kernel_launch(void* const* d_in, const int* in_sizes, int n_in,
                              void* d_out, int out_size)
{
    const float* x_0      = (const float*)d_in[0];
    const float* x_1      = (const float*)d_in[1];
    const int*   gemm     = (const int*)  d_in[2];
    const float* Wa_local = (const float*)d_in[3];
    const float* ba_local = (const float*)d_in[4];
    const float* Wb_local = (const float*)d_in[5];
    const float* bb_local = (const float*)d_in[6];
    const float* Wa_tri   = (const float*)d_in[7];
    const float* ba_tri   = (const float*)d_in[8];
    const float* Wb_tri   = (const float*)d_in[9];
    const float* bb_tri   = (const float*)d_in[10];
    const float* Wa_fuse  = (const float*)d_in[11];
    const float* ba_fuse  = (const float*)d_in[12];
    const float* Wb_fuse  = (const float*)d_in[13];
    const float* bb_fuse  = (const float*)d_in[14];
    float* out = (float*)d_out;

    prep_kernel<<<TR_BLOCKS + W_BLOCKS, 256>>>(
        x_0, x_1,
        Wa_local, ba_local, Wb_local, bb_local,
        Wa_tri, ba_tri, Wb_tri, bb_tri,
        Wa_fuse, ba_fuse, Wb_fuse, bb_fuse);

    mesh_main_kernel<<<296, 256>>>(gemm, out);
}